// round 3
// baseline (speedup 1.0000x reference)
#include <cuda_runtime.h>
#include <cuda_bf16.h>
#include <cuda_fp16.h>
#include <cstdint>

#define BSZ 2
#define NQ 10000
#define EDIM 256
#define NH 8
#define NL 4
#define NP 8
#define DH 32
#define LEN_VAL 13294
#define NOA 768            // fused off(512) + attn(256) output width

// ---------------- scratch (device globals: allocation-free) ----------------
__device__ __half        g_vh[(size_t)BSZ * LEN_VAL * EDIM];     // projected value, fp16
__device__ __nv_bfloat16 g_valh[(size_t)BSZ * LEN_VAL * EDIM];   // raw value split hi
__device__ __nv_bfloat16 g_vall[(size_t)BSZ * LEN_VAL * EDIM];   // raw value split lo
__device__ __nv_bfloat16 g_qh[(size_t)BSZ * NQ * EDIM];
__device__ __nv_bfloat16 g_ql[(size_t)BSZ * NQ * EDIM];
__device__ float         g_offattn[(size_t)BSZ * NQ * NOA];      // [off 512 | attn 256]
__device__ __nv_bfloat16 g_midh[(size_t)BSZ * NQ * EDIM];
__device__ __nv_bfloat16 g_midl[(size_t)BSZ * NQ * EDIM];
__device__ float         g_bias_oa[NOA];

// bf16 hi/lo split weights: [W_val 256x256][W_oa 256x768][W_out 256x256]
#define WOFF_VAL  0
#define WOFF_OA   65536
#define WOFF_OUT  262144
#define WTOTAL    327680
__device__ __nv_bfloat16 g_Wh[WTOTAL];
__device__ __nv_bfloat16 g_Wl[WTOTAL];

__constant__ int c_Hs[NL]    = {100, 50, 25, 13};
__constant__ int c_Ws[NL]    = {100, 50, 25, 13};
__constant__ int c_start[NL] = {0, 10000, 12500, 13125};

// ---------------- helpers ----------------
__device__ __forceinline__ void splitf(float x, __nv_bfloat16& h, __nv_bfloat16& l) {
    h = __float2bfloat16(x);
    l = __float2bfloat16(x - __bfloat162float(h));
}

__device__ __forceinline__ void ldm_x4(uint32_t& r0, uint32_t& r1, uint32_t& r2, uint32_t& r3,
                                       uint32_t addr) {
    asm volatile("ldmatrix.sync.aligned.m8n8.x4.shared.b16 {%0,%1,%2,%3}, [%4];"
                 : "=r"(r0), "=r"(r1), "=r"(r2), "=r"(r3) : "r"(addr));
}

__device__ __forceinline__ void ldm_x4_trans(uint32_t& r0, uint32_t& r1, uint32_t& r2, uint32_t& r3,
                                             uint32_t addr) {
    asm volatile("ldmatrix.sync.aligned.m8n8.x4.trans.shared.b16 {%0,%1,%2,%3}, [%4];"
                 : "=r"(r0), "=r"(r1), "=r"(r2), "=r"(r3) : "r"(addr));
}

__device__ __forceinline__ void mma_bf16(float* d, const uint32_t* a, const uint32_t* b) {
    asm volatile("mma.sync.aligned.m16n8k16.row.col.f32.bf16.bf16.f32 "
                 "{%0,%1,%2,%3},{%4,%5,%6,%7},{%8,%9},{%0,%1,%2,%3};"
                 : "+f"(d[0]), "+f"(d[1]), "+f"(d[2]), "+f"(d[3])
                 : "r"(a[0]), "r"(a[1]), "r"(a[2]), "r"(a[3]), "r"(b[0]), "r"(b[1]));
}

__device__ __forceinline__ void cp_async16(uint32_t dst, const void* src, bool pred) {
    int sz = pred ? 16 : 0;
    asm volatile("cp.async.cg.shared.global [%0], [%1], 16, %2;\n"
                 :: "r"(dst), "l"(src), "r"(sz));
}
#define CP_COMMIT() asm volatile("cp.async.commit_group;\n" ::)
#define CP_WAIT(N)  asm volatile("cp.async.wait_group %0;\n" :: "n"(N))

__device__ __forceinline__ void store2(float* p, float a, float b) {
    *(float2*)p = make_float2(a, b);
}
__device__ __forceinline__ void store2(__half* p, float a, float b) {
    *(__half2*)p = __floats2half2_rn(a, b);
}

// ---------------- prep kernels ----------------
__global__ void split_weights_kernel(const float* __restrict__ W_val,
                                     const float* __restrict__ W_off,
                                     const float* __restrict__ W_attn,
                                     const float* __restrict__ W_out,
                                     const float* __restrict__ b_off,
                                     const float* __restrict__ b_attn) {
    int i = blockIdx.x * blockDim.x + threadIdx.x;
    if (i >= WTOTAL) return;
    float x;
    if (i < WOFF_OA) {
        x = W_val[i];
    } else if (i < WOFF_OUT) {
        int j = i - WOFF_OA;
        int r = j / NOA, c = j - r * NOA;
        x = (c < 512) ? W_off[r * 512 + c] : W_attn[r * 256 + (c - 512)];
    } else {
        x = W_out[i - WOFF_OUT];
    }
    __nv_bfloat16 h, l;
    splitf(x, h, l);
    g_Wh[i] = h; g_Wl[i] = l;
    if (i < NOA) g_bias_oa[i] = (i < 512) ? b_off[i] : b_attn[i - 512];
}

__global__ void add_pos_split_kernel(const float* __restrict__ a,
                                     const float* __restrict__ b, int n) {
    int i = blockIdx.x * blockDim.x + threadIdx.x;
    if (i < n) {
        __nv_bfloat16 h, l;
        splitf(a[i] + b[i], h, l);
        g_qh[i] = h; g_ql[i] = l;
    }
}

__global__ void split_value_kernel(const float* __restrict__ v, int n) {
    int i = blockIdx.x * blockDim.x + threadIdx.x;
    if (i < n) {
        __nv_bfloat16 h, l;
        splitf(v[i], h, l);
        g_valh[i] = h; g_vall[i] = l;
    }
}

// ---------------- bf16x3 tensor-core GEMM, cp.async 4-stage pipeline ----------------
// C[M,N] = (Ah+Al)[M,K] @ (Bh+Bl)[K,N] + bias   (Al*Bl dropped)
// BM=128, BN=128, BK=32, 512 threads, warp tile 32x32.
#define SA_STRIDE 40                     // halfs per A row (32 + 8 pad)
#define SB_STRIDE 136                    // halfs per B row (128 + 8 pad)
#define SA_BYTES  (128 * SA_STRIDE * 2)  // 10240 per stage
#define SB_BYTES  (32 * SB_STRIDE * 2)   // 8704 per stage
#define NSTAGE 4
#define OFF_AH 0
#define OFF_AL (NSTAGE * SA_BYTES)
#define OFF_BH (2 * NSTAGE * SA_BYTES)
#define OFF_BL (2 * NSTAGE * SA_BYTES + NSTAGE * SB_BYTES)
#define GEMM_SMEM (2 * NSTAGE * SA_BYTES + 2 * NSTAGE * SB_BYTES)  // 151552

template <typename TOut>
__global__ void __launch_bounds__(512, 1)
gemm_bf16x3_kernel(const __nv_bfloat16* __restrict__ Ah,
                   const __nv_bfloat16* __restrict__ Al,
                   const __nv_bfloat16* __restrict__ Bh,
                   const __nv_bfloat16* __restrict__ Bl,
                   const float* __restrict__ bias,
                   TOut* __restrict__ C,
                   int M, int N, int K) {
    extern __shared__ char smem_raw[];
    const uint32_t sbase = (uint32_t)__cvta_generic_to_shared(smem_raw);

    const int tid  = threadIdx.x;
    const int lane = tid & 31;
    const int wid  = tid >> 5;
    const int warp_m = wid & 3;
    const int warp_n = wid >> 2;

    const int row0 = blockIdx.y * 128;
    const int col0 = blockIdx.x * 128;

    // cp.async mappings
    const int a_row = tid >> 2;            // 0..127
    const int a_c8  = (tid & 3) * 8;       // 0,8,16,24
    const int b_kr  = tid >> 4;            // 0..31
    const int b_c8  = (tid & 15) * 8;      // 0..120

    const bool a_pred = (row0 + a_row) < M;
    const __nv_bfloat16* srcAh = Ah + (size_t)(row0 + a_row) * K + a_c8;
    const __nv_bfloat16* srcAl = Al + (size_t)(row0 + a_row) * K + a_c8;
    const __nv_bfloat16* srcBh = Bh + (size_t)b_kr * N + col0 + b_c8;
    const __nv_bfloat16* srcBl = Bl + (size_t)b_kr * N + col0 + b_c8;

    const uint32_t dA = sbase + a_row * (SA_STRIDE * 2) + a_c8 * 2;
    const uint32_t dB = sbase + b_kr * (SB_STRIDE * 2) + b_c8 * 2;

    const int NK = K >> 5;   // 8

#define ISSUE(J)                                                             \
    {                                                                        \
        int s = (J) & (NSTAGE - 1);                                          \
        int k0 = (J) * 32;                                                   \
        cp_async16(dA + OFF_AH + s * SA_BYTES, srcAh + k0, a_pred);          \
        cp_async16(dA + OFF_AL + s * SA_BYTES, srcAl + k0, a_pred);          \
        cp_async16(dB + OFF_BH + s * SB_BYTES, srcBh + (size_t)k0 * N, true);\
        cp_async16(dB + OFF_BL + s * SB_BYTES, srcBl + (size_t)k0 * N, true);\
    }

    ISSUE(0); CP_COMMIT();
    ISSUE(1); CP_COMMIT();
    ISSUE(2); CP_COMMIT();

    float acc[2][4][4];
#pragma unroll
    for (int mt = 0; mt < 2; mt++)
#pragma unroll
        for (int nb = 0; nb < 4; nb++)
#pragma unroll
            for (int j = 0; j < 4; j++) acc[mt][nb][j] = 0.f;

    for (int it = 0; it < NK; ++it) {
        CP_WAIT(2);
        __syncthreads();
        if (it + 3 < NK) ISSUE(it + 3);
        CP_COMMIT();

        const int s = it & (NSTAGE - 1);
        const uint32_t aHB = sbase + OFF_AH + s * SA_BYTES;
        const uint32_t aLB = sbase + OFF_AL + s * SA_BYTES;
        const uint32_t bHB = sbase + OFF_BH + s * SB_BYTES;
        const uint32_t bLB = sbase + OFF_BL + s * SB_BYTES;

#pragma unroll
        for (int ks = 0; ks < 2; ks++) {
            uint32_t ah[2][4], al[2][4], bh[4][2], bl[4][2];
#pragma unroll
            for (int mt = 0; mt < 2; mt++) {
                int row = warp_m * 32 + mt * 16 + (lane & 15);
                int col = ks * 16 + ((lane >> 4) << 3);
                uint32_t off = row * (SA_STRIDE * 2) + col * 2;
                ldm_x4(ah[mt][0], ah[mt][1], ah[mt][2], ah[mt][3], aHB + off);
                ldm_x4(al[mt][0], al[mt][1], al[mt][2], al[mt][3], aLB + off);
            }
#pragma unroll
            for (int g = 0; g < 2; g++) {
                int kk = ks * 16 + ((lane >> 3) & 1) * 8 + (lane & 7);
                int nn = warp_n * 32 + g * 16 + ((lane >> 4) & 1) * 8;
                uint32_t off = kk * (SB_STRIDE * 2) + nn * 2;
                uint32_t r0, r1, r2, r3;
                ldm_x4_trans(r0, r1, r2, r3, bHB + off);
                bh[2 * g][0] = r0; bh[2 * g][1] = r1;
                bh[2 * g + 1][0] = r2; bh[2 * g + 1][1] = r3;
                ldm_x4_trans(r0, r1, r2, r3, bLB + off);
                bl[2 * g][0] = r0; bl[2 * g][1] = r1;
                bl[2 * g + 1][0] = r2; bl[2 * g + 1][1] = r3;
            }
#pragma unroll
            for (int mt = 0; mt < 2; mt++)
#pragma unroll
                for (int nb = 0; nb < 4; nb++) {
                    mma_bf16(acc[mt][nb], ah[mt], bh[nb]);
                    mma_bf16(acc[mt][nb], ah[mt], bl[nb]);
                    mma_bf16(acc[mt][nb], al[mt], bh[nb]);
                }
        }
        __syncthreads();
    }
#undef ISSUE

    // epilogue with bias
#pragma unroll
    for (int mt = 0; mt < 2; mt++) {
#pragma unroll
        for (int nb = 0; nb < 4; nb++) {
            int gn = col0 + warp_n * 32 + nb * 8 + (lane & 3) * 2;
            float b0 = bias[gn], b1 = bias[gn + 1];
            int gm0 = row0 + warp_m * 32 + mt * 16 + (lane >> 2);
            if (gm0 < M) store2(C + (size_t)gm0 * N + gn, acc[mt][nb][0] + b0, acc[mt][nb][1] + b1);
            int gm1 = gm0 + 8;
            if (gm1 < M) store2(C + (size_t)gm1 * N + gn, acc[mt][nb][2] + b0, acc[mt][nb][3] + b1);
        }
    }
}

// ---------------- deformable sampling ----------------
// One warp per (b, n, h). Lane i owns sample i (l = i>>3, p = i&7).
__global__ void sample_kernel(const float* __restrict__ ref) {
    int gw = (blockIdx.x * blockDim.x + threadIdx.x) >> 5;
    int lane = threadIdx.x & 31;
    if (gw >= BSZ * NQ * NH) return;

    int h = gw & (NH - 1);
    int n = (gw >> 3) % NQ;
    int b = gw / (NQ * NH);

    int l = lane >> 3;
    int Hs = c_Hs[l], Ws = c_Ws[l];

    long qrow = (long)b * NQ + n;
    const float* oa = g_offattn + qrow * NOA;

    int ocol = ((h * NL + l) * NP + (lane & 7)) * 2;
    float ox = oa[ocol];
    float oy = oa[ocol + 1];
    float rx = ref[(qrow * NL + l) * 2 + 0];
    float ry = ref[(qrow * NL + l) * 2 + 1];

    float x = rx * (float)Ws + ox - 0.5f;
    float y = ry * (float)Hs + oy - 0.5f;

    float fx0 = floorf(x), fy0 = floorf(y);
    int x0 = (int)fx0, y0 = (int)fy0;
    float wx1 = x - fx0, wy1 = y - fy0;
    float wx0 = 1.f - wx1, wy0 = 1.f - wy1;

    float logit = oa[512 + h * DH + lane];
    float m = logit;
#pragma unroll
    for (int o = 16; o; o >>= 1) m = fmaxf(m, __shfl_xor_sync(0xFFFFFFFFu, m, o));
    float ex = __expf(logit - m);
    float s = ex;
#pragma unroll
    for (int o = 16; o; o >>= 1) s += __shfl_xor_sync(0xFFFFFFFFu, s, o);
    float aw = ex / s;

    int x1 = x0 + 1, y1 = y0 + 1;
    bool vx0 = (x0 >= 0) && (x0 < Ws);
    bool vx1 = (x1 >= 0) && (x1 < Ws);
    bool vy0 = (y0 >= 0) && (y0 < Hs);
    bool vy1 = (y1 >= 0) && (y1 < Hs);

    int base = (b * LEN_VAL + c_start[l]) * EDIM + h * DH;

    int p00 = (vy0 && vx0) ? (y0 * Ws + x0) : 0;
    int p01 = (vy0 && vx1) ? (y0 * Ws + x1) : 0;
    int p10 = (vy1 && vx0) ? (y1 * Ws + x0) : 0;
    int p11 = (vy1 && vx1) ? (y1 * Ws + x1) : 0;

    float w00 = (vy0 && vx0) ? aw * wx0 * wy0 : 0.f;
    float w01 = (vy0 && vx1) ? aw * wx1 * wy0 : 0.f;
    float w10 = (vy1 && vx0) ? aw * wx0 * wy1 : 0.f;
    float w11 = (vy1 && vx1) ? aw * wx1 * wy1 : 0.f;

    int o00 = base + p00 * EDIM;
    int o01 = base + p01 * EDIM;
    int o10 = base + p10 * EDIM;
    int o11 = base + p11 * EDIM;

    float acc = 0.f;
#pragma unroll 4
    for (int sIdx = 0; sIdx < 32; sIdx++) {
        int a0 = __shfl_sync(0xFFFFFFFFu, o00, sIdx);
        int a1 = __shfl_sync(0xFFFFFFFFu, o01, sIdx);
        int a2 = __shfl_sync(0xFFFFFFFFu, o10, sIdx);
        int a3 = __shfl_sync(0xFFFFFFFFu, o11, sIdx);
        float u0 = __shfl_sync(0xFFFFFFFFu, w00, sIdx);
        float u1 = __shfl_sync(0xFFFFFFFFu, w01, sIdx);
        float u2 = __shfl_sync(0xFFFFFFFFu, w10, sIdx);
        float u3 = __shfl_sync(0xFFFFFFFFu, w11, sIdx);
        float v0 = __half2float(g_vh[a0 + lane]);
        float v1 = __half2float(g_vh[a1 + lane]);
        float v2 = __half2float(g_vh[a2 + lane]);
        float v3 = __half2float(g_vh[a3 + lane]);
        acc += u0 * v0 + u1 * v1 + u2 * v2 + u3 * v3;
    }
    __nv_bfloat16 hh, ll;
    splitf(acc, hh, ll);
    size_t midx = qrow * EDIM + h * DH + lane;
    g_midh[midx] = hh;
    g_midl[midx] = ll;
}

// ---------------- launch ----------------
extern "C" void kernel_launch(void* const* d_in, const int* in_sizes, int n_in,
                              void* d_out, int out_size) {
    const float* query   = (const float*)d_in[0];
    const float* value   = (const float*)d_in[1];
    const float* qpos    = (const float*)d_in[2];
    const float* refpts  = (const float*)d_in[3];
    const float* W_off   = (const float*)d_in[5];
    const float* b_off   = (const float*)d_in[6];
    const float* W_attn  = (const float*)d_in[7];
    const float* b_attn  = (const float*)d_in[8];
    const float* W_val   = (const float*)d_in[9];
    const float* b_val   = (const float*)d_in[10];
    const float* W_out   = (const float*)d_in[11];
    const float* b_out   = (const float*)d_in[12];
    float* out = (float*)d_out;

    __nv_bfloat16 *wh, *wl, *qh, *ql, *valh, *vall, *midh, *midl;
    __half* vh;
    float *voa, *boa;
    cudaGetSymbolAddress((void**)&wh, g_Wh);
    cudaGetSymbolAddress((void**)&wl, g_Wl);
    cudaGetSymbolAddress((void**)&qh, g_qh);
    cudaGetSymbolAddress((void**)&ql, g_ql);
    cudaGetSymbolAddress((void**)&valh, g_valh);
    cudaGetSymbolAddress((void**)&vall, g_vall);
    cudaGetSymbolAddress((void**)&midh, g_midh);
    cudaGetSymbolAddress((void**)&midl, g_midl);
    cudaGetSymbolAddress((void**)&vh, g_vh);
    cudaGetSymbolAddress((void**)&voa, g_offattn);
    cudaGetSymbolAddress((void**)&boa, g_bias_oa);

    cudaFuncSetAttribute(gemm_bf16x3_kernel<float>,
                         cudaFuncAttributeMaxDynamicSharedMemorySize, GEMM_SMEM);
    cudaFuncSetAttribute(gemm_bf16x3_kernel<__half>,
                         cudaFuncAttributeMaxDynamicSharedMemorySize, GEMM_SMEM);

    // 0) split weights + fused bias
    split_weights_kernel<<<(WTOTAL + 255) / 256, 256>>>(W_val, W_off, W_attn, W_out,
                                                        b_off, b_attn);
    // 1) q = query + query_pos (split bf16)
    {
        int n = BSZ * NQ * EDIM;
        add_pos_split_kernel<<<(n + 255) / 256, 256>>>(query, qpos, n);
    }
    // 1b) split raw value
    {
        int n = BSZ * LEN_VAL * EDIM;
        split_value_kernel<<<(n + 255) / 256, 256>>>(value, n);
    }
    // 2) v = value @ W_val + b_val -> fp16
    {
        int M = BSZ * LEN_VAL, N = EDIM, K = EDIM;
        dim3 grid(N / 128, (M + 127) / 128);
        gemm_bf16x3_kernel<__half><<<grid, 512, GEMM_SMEM>>>(
            valh, vall, wh + WOFF_VAL, wl + WOFF_VAL, b_val, vh, M, N, K);
    }
    // 3) [off|attn] = q @ W_oa + b_oa   (N = 768, fused)
    {
        int M = BSZ * NQ, N = NOA, K = EDIM;
        dim3 grid(N / 128, (M + 127) / 128);
        gemm_bf16x3_kernel<float><<<grid, 512, GEMM_SMEM>>>(
            qh, ql, wh + WOFF_OA, wl + WOFF_OA, boa, voa, M, N, K);
    }
    // 4) deformable sampling -> g_mid (split bf16)
    {
        int warps = BSZ * NQ * NH;
        int blocks = (warps * 32 + 255) / 256;
        sample_kernel<<<blocks, 256>>>(refpts);
    }
    // 5) out = mid @ W_out + b_out
    {
        int M = BSZ * NQ, N = EDIM, K = EDIM;
        dim3 grid(N / 128, (M + 127) / 128);
        gemm_bf16x3_kernel<float><<<grid, 512, GEMM_SMEM>>>(
            midh, midl, wh + WOFF_OUT, wl + WOFF_OUT, b_out, out, M, N, K);
    }
}

// round 4
// speedup vs baseline: 1.3576x; 1.3576x over previous
#include <cuda_runtime.h>
#include <cuda_bf16.h>
#include <cuda_fp16.h>
#include <cstdint>

#define BSZ 2
#define NQ 10000
#define EDIM 256
#define NH 8
#define NL 4
#define NP 8
#define DH 32
#define LEN_VAL 13294
#define NOA 768            // fused off(512) + attn(256) output width

// ---------------- scratch (device globals: allocation-free) ----------------
__device__ __half        g_vh[(size_t)BSZ * LEN_VAL * EDIM];     // projected value, fp16
__device__ __nv_bfloat16 g_valh[(size_t)BSZ * LEN_VAL * EDIM];   // raw value split hi
__device__ __nv_bfloat16 g_vall[(size_t)BSZ * LEN_VAL * EDIM];   // raw value split lo
__device__ __nv_bfloat16 g_qh[(size_t)BSZ * NQ * EDIM];
__device__ __nv_bfloat16 g_ql[(size_t)BSZ * NQ * EDIM];
__device__ float         g_offattn[(size_t)BSZ * NQ * NOA];      // [off 512 | attn 256]
__device__ __nv_bfloat16 g_midh[(size_t)BSZ * NQ * EDIM];
__device__ __nv_bfloat16 g_midl[(size_t)BSZ * NQ * EDIM];
__device__ float         g_bias_oa[NOA];

// bf16 hi/lo split weights: [W_val 256x256][W_oa 256x768][W_out 256x256]
#define WOFF_VAL  0
#define WOFF_OA   65536
#define WOFF_OUT  262144
#define WTOTAL    327680
__device__ __nv_bfloat16 g_Wh[WTOTAL];
__device__ __nv_bfloat16 g_Wl[WTOTAL];

__constant__ int c_Hs[NL]    = {100, 50, 25, 13};
__constant__ int c_Ws[NL]    = {100, 50, 25, 13};
__constant__ int c_start[NL] = {0, 10000, 12500, 13125};

// ---------------- helpers ----------------
__device__ __forceinline__ void splitf(float x, __nv_bfloat16& h, __nv_bfloat16& l) {
    h = __float2bfloat16(x);
    l = __float2bfloat16(x - __bfloat162float(h));
}

__device__ __forceinline__ void ldm_x4(uint32_t& r0, uint32_t& r1, uint32_t& r2, uint32_t& r3,
                                       uint32_t addr) {
    asm volatile("ldmatrix.sync.aligned.m8n8.x4.shared.b16 {%0,%1,%2,%3}, [%4];"
                 : "=r"(r0), "=r"(r1), "=r"(r2), "=r"(r3) : "r"(addr));
}

__device__ __forceinline__ void ldm_x4_trans(uint32_t& r0, uint32_t& r1, uint32_t& r2, uint32_t& r3,
                                             uint32_t addr) {
    asm volatile("ldmatrix.sync.aligned.m8n8.x4.trans.shared.b16 {%0,%1,%2,%3}, [%4];"
                 : "=r"(r0), "=r"(r1), "=r"(r2), "=r"(r3) : "r"(addr));
}

__device__ __forceinline__ void mma_bf16(float* d, const uint32_t* a, const uint32_t* b) {
    asm volatile("mma.sync.aligned.m16n8k16.row.col.f32.bf16.bf16.f32 "
                 "{%0,%1,%2,%3},{%4,%5,%6,%7},{%8,%9},{%0,%1,%2,%3};"
                 : "+f"(d[0]), "+f"(d[1]), "+f"(d[2]), "+f"(d[3])
                 : "r"(a[0]), "r"(a[1]), "r"(a[2]), "r"(a[3]), "r"(b[0]), "r"(b[1]));
}

__device__ __forceinline__ void cp_async16(uint32_t dst, const void* src, bool pred) {
    int sz = pred ? 16 : 0;
    asm volatile("cp.async.cg.shared.global [%0], [%1], 16, %2;\n"
                 :: "r"(dst), "l"(src), "r"(sz));
}
#define CP_COMMIT() asm volatile("cp.async.commit_group;\n" ::)
#define CP_WAIT(N)  asm volatile("cp.async.wait_group %0;\n" :: "n"(N))

__device__ __forceinline__ void store2(float* p, float a, float b) {
    *(float2*)p = make_float2(a, b);
}
__device__ __forceinline__ void store2(__half* p, float a, float b) {
    *(__half2*)p = __floats2half2_rn(a, b);
}

// ---------------- prep kernels ----------------
__global__ void split_weights_kernel(const float* __restrict__ W_val,
                                     const float* __restrict__ W_off,
                                     const float* __restrict__ W_attn,
                                     const float* __restrict__ W_out,
                                     const float* __restrict__ b_off,
                                     const float* __restrict__ b_attn) {
    int i = blockIdx.x * blockDim.x + threadIdx.x;
    if (i >= WTOTAL) return;
    float x;
    if (i < WOFF_OA) {
        x = W_val[i];
    } else if (i < WOFF_OUT) {
        int j = i - WOFF_OA;
        int r = j / NOA, c = j - r * NOA;
        x = (c < 512) ? W_off[r * 512 + c] : W_attn[r * 256 + (c - 512)];
    } else {
        x = W_out[i - WOFF_OUT];
    }
    __nv_bfloat16 h, l;
    splitf(x, h, l);
    g_Wh[i] = h; g_Wl[i] = l;
    if (i < NOA) g_bias_oa[i] = (i < 512) ? b_off[i] : b_attn[i - 512];
}

__global__ void add_pos_split_kernel(const float* __restrict__ a,
                                     const float* __restrict__ b, int n) {
    int i = blockIdx.x * blockDim.x + threadIdx.x;
    if (i < n) {
        __nv_bfloat16 h, l;
        splitf(a[i] + b[i], h, l);
        g_qh[i] = h; g_ql[i] = l;
    }
}

__global__ void split_value_kernel(const float* __restrict__ v, int n) {
    int i = blockIdx.x * blockDim.x + threadIdx.x;
    if (i < n) {
        __nv_bfloat16 h, l;
        splitf(v[i], h, l);
        g_valh[i] = h; g_vall[i] = l;
    }
}

// ---------------- bf16x3 tensor-core GEMM, cp.async 4-stage pipeline ----------------
#define SA_STRIDE 40
#define SB_STRIDE 136
#define SA_BYTES  (128 * SA_STRIDE * 2)
#define SB_BYTES  (32 * SB_STRIDE * 2)
#define NSTAGE 4
#define OFF_AH 0
#define OFF_AL (NSTAGE * SA_BYTES)
#define OFF_BH (2 * NSTAGE * SA_BYTES)
#define OFF_BL (2 * NSTAGE * SA_BYTES + NSTAGE * SB_BYTES)
#define GEMM_SMEM (2 * NSTAGE * SA_BYTES + 2 * NSTAGE * SB_BYTES)

template <typename TOut>
__global__ void __launch_bounds__(512, 1)
gemm_bf16x3_kernel(const __nv_bfloat16* __restrict__ Ah,
                   const __nv_bfloat16* __restrict__ Al,
                   const __nv_bfloat16* __restrict__ Bh,
                   const __nv_bfloat16* __restrict__ Bl,
                   const float* __restrict__ bias,
                   TOut* __restrict__ C,
                   int M, int N, int K) {
    extern __shared__ char smem_raw[];
    const uint32_t sbase = (uint32_t)__cvta_generic_to_shared(smem_raw);

    const int tid  = threadIdx.x;
    const int lane = tid & 31;
    const int wid  = tid >> 5;
    const int warp_m = wid & 3;
    const int warp_n = wid >> 2;

    const int row0 = blockIdx.y * 128;
    const int col0 = blockIdx.x * 128;

    const int a_row = tid >> 2;
    const int a_c8  = (tid & 3) * 8;
    const int b_kr  = tid >> 4;
    const int b_c8  = (tid & 15) * 8;

    const bool a_pred = (row0 + a_row) < M;
    const __nv_bfloat16* srcAh = Ah + (size_t)(row0 + a_row) * K + a_c8;
    const __nv_bfloat16* srcAl = Al + (size_t)(row0 + a_row) * K + a_c8;
    const __nv_bfloat16* srcBh = Bh + (size_t)b_kr * N + col0 + b_c8;
    const __nv_bfloat16* srcBl = Bl + (size_t)b_kr * N + col0 + b_c8;

    const uint32_t dA = sbase + a_row * (SA_STRIDE * 2) + a_c8 * 2;
    const uint32_t dB = sbase + b_kr * (SB_STRIDE * 2) + b_c8 * 2;

    const int NK = K >> 5;

#define ISSUE(J)                                                             \
    {                                                                        \
        int s = (J) & (NSTAGE - 1);                                          \
        int k0 = (J) * 32;                                                   \
        cp_async16(dA + OFF_AH + s * SA_BYTES, srcAh + k0, a_pred);          \
        cp_async16(dA + OFF_AL + s * SA_BYTES, srcAl + k0, a_pred);          \
        cp_async16(dB + OFF_BH + s * SB_BYTES, srcBh + (size_t)k0 * N, true);\
        cp_async16(dB + OFF_BL + s * SB_BYTES, srcBl + (size_t)k0 * N, true);\
    }

    ISSUE(0); CP_COMMIT();
    ISSUE(1); CP_COMMIT();
    ISSUE(2); CP_COMMIT();

    float acc[2][4][4];
#pragma unroll
    for (int mt = 0; mt < 2; mt++)
#pragma unroll
        for (int nb = 0; nb < 4; nb++)
#pragma unroll
            for (int j = 0; j < 4; j++) acc[mt][nb][j] = 0.f;

    for (int it = 0; it < NK; ++it) {
        CP_WAIT(2);
        __syncthreads();
        if (it + 3 < NK) ISSUE(it + 3);
        CP_COMMIT();

        const int s = it & (NSTAGE - 1);
        const uint32_t aHB = sbase + OFF_AH + s * SA_BYTES;
        const uint32_t aLB = sbase + OFF_AL + s * SA_BYTES;
        const uint32_t bHB = sbase + OFF_BH + s * SB_BYTES;
        const uint32_t bLB = sbase + OFF_BL + s * SB_BYTES;

#pragma unroll
        for (int ks = 0; ks < 2; ks++) {
            uint32_t ah[2][4], al[2][4], bh[4][2], bl[4][2];
#pragma unroll
            for (int mt = 0; mt < 2; mt++) {
                int row = warp_m * 32 + mt * 16 + (lane & 15);
                int col = ks * 16 + ((lane >> 4) << 3);
                uint32_t off = row * (SA_STRIDE * 2) + col * 2;
                ldm_x4(ah[mt][0], ah[mt][1], ah[mt][2], ah[mt][3], aHB + off);
                ldm_x4(al[mt][0], al[mt][1], al[mt][2], al[mt][3], aLB + off);
            }
#pragma unroll
            for (int g = 0; g < 2; g++) {
                int kk = ks * 16 + ((lane >> 3) & 1) * 8 + (lane & 7);
                int nn = warp_n * 32 + g * 16 + ((lane >> 4) & 1) * 8;
                uint32_t off = kk * (SB_STRIDE * 2) + nn * 2;
                uint32_t r0, r1, r2, r3;
                ldm_x4_trans(r0, r1, r2, r3, bHB + off);
                bh[2 * g][0] = r0; bh[2 * g][1] = r1;
                bh[2 * g + 1][0] = r2; bh[2 * g + 1][1] = r3;
                ldm_x4_trans(r0, r1, r2, r3, bLB + off);
                bl[2 * g][0] = r0; bl[2 * g][1] = r1;
                bl[2 * g + 1][0] = r2; bl[2 * g + 1][1] = r3;
            }
#pragma unroll
            for (int mt = 0; mt < 2; mt++)
#pragma unroll
                for (int nb = 0; nb < 4; nb++) {
                    mma_bf16(acc[mt][nb], ah[mt], bh[nb]);
                    mma_bf16(acc[mt][nb], ah[mt], bl[nb]);
                    mma_bf16(acc[mt][nb], al[mt], bh[nb]);
                }
        }
        __syncthreads();
    }
#undef ISSUE

#pragma unroll
    for (int mt = 0; mt < 2; mt++) {
#pragma unroll
        for (int nb = 0; nb < 4; nb++) {
            int gn = col0 + warp_n * 32 + nb * 8 + (lane & 3) * 2;
            float b0 = bias[gn], b1 = bias[gn + 1];
            int gm0 = row0 + warp_m * 32 + mt * 16 + (lane >> 2);
            if (gm0 < M) store2(C + (size_t)gm0 * N + gn, acc[mt][nb][0] + b0, acc[mt][nb][1] + b1);
            int gm1 = gm0 + 8;
            if (gm1 < M) store2(C + (size_t)gm1 * N + gn, acc[mt][nb][2] + b0, acc[mt][nb][3] + b1);
        }
    }
}

// ---------------- deformable sampling v2 (smem metadata, no shfl broadcast) ----------------
// Block = 256 threads = 8 warps, one warp per (b,n,h) group.
// Phase 1: lane i computes sample i's corner addresses + attention-folded weights -> smem.
// Phase 2: 16 lanes per sample, 2 samples in flight; lane owns channels (2c, 2c+1)
//          loaded as __half2; float2 accumulator; final cross-half shfl reduction.
__global__ void __launch_bounds__(256)
sample_kernel(const float* __restrict__ ref) {
    __shared__ int4   s_ad[8][32];
    __shared__ float4 s_w[8][32];

    const int wlocal = threadIdx.x >> 5;
    const int lane   = threadIdx.x & 31;
    const int gw = blockIdx.x * 8 + wlocal;     // group = (b,n,h); grid covers exactly

    const int h = gw & (NH - 1);
    const int n = (gw >> 3) % NQ;
    const int b = gw / (NQ * NH);
    const long qrow = (long)b * NQ + n;
    const float* oa = g_offattn + qrow * NOA;

    // ---- phase 1: lane = sample (l = lane>>3, p = lane&7) ----
    {
        int l = lane >> 3;
        int Hs = c_Hs[l], Ws = c_Ws[l];
        int ocol = ((h * NL + l) * NP + (lane & 7)) * 2;
        float ox = oa[ocol];
        float oy = oa[ocol + 1];
        float rx = ref[(qrow * NL + l) * 2 + 0];
        float ry = ref[(qrow * NL + l) * 2 + 1];

        float x = rx * (float)Ws + ox - 0.5f;
        float y = ry * (float)Hs + oy - 0.5f;

        float fx0 = floorf(x), fy0 = floorf(y);
        int x0 = (int)fx0, y0 = (int)fy0;
        float wx1 = x - fx0, wy1 = y - fy0;
        float wx0 = 1.f - wx1, wy0 = 1.f - wy1;

        float logit = oa[512 + h * DH + lane];
        float m = logit;
#pragma unroll
        for (int o = 16; o; o >>= 1) m = fmaxf(m, __shfl_xor_sync(0xFFFFFFFFu, m, o));
        float ex = __expf(logit - m);
        float s = ex;
#pragma unroll
        for (int o = 16; o; o >>= 1) s += __shfl_xor_sync(0xFFFFFFFFu, s, o);
        float aw = ex / s;

        int x1 = x0 + 1, y1 = y0 + 1;
        bool vx0 = (x0 >= 0) && (x0 < Ws);
        bool vx1 = (x1 >= 0) && (x1 < Ws);
        bool vy0 = (y0 >= 0) && (y0 < Hs);
        bool vy1 = (y1 >= 0) && (y1 < Hs);

        int base = (b * LEN_VAL + c_start[l]) * EDIM + h * DH;

        int p00 = (vy0 && vx0) ? (y0 * Ws + x0) : 0;
        int p01 = (vy0 && vx1) ? (y0 * Ws + x1) : 0;
        int p10 = (vy1 && vx0) ? (y1 * Ws + x0) : 0;
        int p11 = (vy1 && vx1) ? (y1 * Ws + x1) : 0;

        float w00 = (vy0 && vx0) ? aw * wx0 * wy0 : 0.f;
        float w01 = (vy0 && vx1) ? aw * wx1 * wy0 : 0.f;
        float w10 = (vy1 && vx0) ? aw * wx0 * wy1 : 0.f;
        float w11 = (vy1 && vx1) ? aw * wx1 * wy1 : 0.f;

        s_ad[wlocal][lane] = make_int4(base + p00 * EDIM, base + p01 * EDIM,
                                       base + p10 * EDIM, base + p11 * EDIM);
        s_w[wlocal][lane]  = make_float4(w00, w01, w10, w11);
    }
    __syncwarp();

    // ---- phase 2: gather ----
    const int half = lane >> 4;     // sample parity
    const int c    = lane & 15;     // channel-pair index (channels 2c, 2c+1)
    const __half2* vp = (const __half2*)g_vh;

    float2 acc = make_float2(0.f, 0.f);
#pragma unroll
    for (int it = 0; it < 16; it++) {
        int sIdx = it * 2 + half;
        int4   ad = s_ad[wlocal][sIdx];
        float4 ww = s_w[wlocal][sIdx];
        float2 f;
        f = __half22float2(vp[(ad.x >> 1) + c]);
        acc.x = fmaf(ww.x, f.x, acc.x); acc.y = fmaf(ww.x, f.y, acc.y);
        f = __half22float2(vp[(ad.y >> 1) + c]);
        acc.x = fmaf(ww.y, f.x, acc.x); acc.y = fmaf(ww.y, f.y, acc.y);
        f = __half22float2(vp[(ad.z >> 1) + c]);
        acc.x = fmaf(ww.z, f.x, acc.x); acc.y = fmaf(ww.z, f.y, acc.y);
        f = __half22float2(vp[(ad.w >> 1) + c]);
        acc.x = fmaf(ww.w, f.x, acc.x); acc.y = fmaf(ww.w, f.y, acc.y);
    }

    // combine even/odd sample partial sums (lanes c and c+16 hold the two halves)
    acc.x += __shfl_xor_sync(0xFFFFFFFFu, acc.x, 16);
    acc.y += __shfl_xor_sync(0xFFFFFFFFu, acc.y, 16);

    if (half == 0) {
        size_t midx = qrow * EDIM + h * DH + c * 2;
        __nv_bfloat16 h0, l0, h1, l1;
        splitf(acc.x, h0, l0);
        splitf(acc.y, h1, l1);
        *(__nv_bfloat162*)(g_midh + midx) = __halves2bfloat162(h0, h1);
        *(__nv_bfloat162*)(g_midl + midx) = __halves2bfloat162(l0, l1);
    }
}

// ---------------- launch ----------------
extern "C" void kernel_launch(void* const* d_in, const int* in_sizes, int n_in,
                              void* d_out, int out_size) {
    const float* query   = (const float*)d_in[0];
    const float* value   = (const float*)d_in[1];
    const float* qpos    = (const float*)d_in[2];
    const float* refpts  = (const float*)d_in[3];
    const float* W_off   = (const float*)d_in[5];
    const float* b_off   = (const float*)d_in[6];
    const float* W_attn  = (const float*)d_in[7];
    const float* b_attn  = (const float*)d_in[8];
    const float* W_val   = (const float*)d_in[9];
    const float* b_val   = (const float*)d_in[10];
    const float* W_out   = (const float*)d_in[11];
    const float* b_out   = (const float*)d_in[12];
    float* out = (float*)d_out;

    __nv_bfloat16 *wh, *wl, *qh, *ql, *valh, *vall, *midh, *midl;
    __half* vh;
    float *voa, *boa;
    cudaGetSymbolAddress((void**)&wh, g_Wh);
    cudaGetSymbolAddress((void**)&wl, g_Wl);
    cudaGetSymbolAddress((void**)&qh, g_qh);
    cudaGetSymbolAddress((void**)&ql, g_ql);
    cudaGetSymbolAddress((void**)&valh, g_valh);
    cudaGetSymbolAddress((void**)&vall, g_vall);
    cudaGetSymbolAddress((void**)&midh, g_midh);
    cudaGetSymbolAddress((void**)&midl, g_midl);
    cudaGetSymbolAddress((void**)&vh, g_vh);
    cudaGetSymbolAddress((void**)&voa, g_offattn);
    cudaGetSymbolAddress((void**)&boa, g_bias_oa);

    cudaFuncSetAttribute(gemm_bf16x3_kernel<float>,
                         cudaFuncAttributeMaxDynamicSharedMemorySize, GEMM_SMEM);
    cudaFuncSetAttribute(gemm_bf16x3_kernel<__half>,
                         cudaFuncAttributeMaxDynamicSharedMemorySize, GEMM_SMEM);

    // 0) split weights + fused bias
    split_weights_kernel<<<(WTOTAL + 255) / 256, 256>>>(W_val, W_off, W_attn, W_out,
                                                        b_off, b_attn);
    // 1) q = query + query_pos (split bf16)
    {
        int n = BSZ * NQ * EDIM;
        add_pos_split_kernel<<<(n + 255) / 256, 256>>>(query, qpos, n);
    }
    // 1b) split raw value
    {
        int n = BSZ * LEN_VAL * EDIM;
        split_value_kernel<<<(n + 255) / 256, 256>>>(value, n);
    }
    // 2) v = value @ W_val + b_val -> fp16
    {
        int M = BSZ * LEN_VAL, N = EDIM, K = EDIM;
        dim3 grid(N / 128, (M + 127) / 128);
        gemm_bf16x3_kernel<__half><<<grid, 512, GEMM_SMEM>>>(
            valh, vall, wh + WOFF_VAL, wl + WOFF_VAL, b_val, vh, M, N, K);
    }
    // 3) [off|attn] = q @ W_oa + b_oa (N = 768, fused)
    {
        int M = BSZ * NQ, N = NOA, K = EDIM;
        dim3 grid(N / 128, (M + 127) / 128);
        gemm_bf16x3_kernel<float><<<grid, 512, GEMM_SMEM>>>(
            qh, ql, wh + WOFF_OA, wl + WOFF_OA, boa, voa, M, N, K);
    }
    // 4) deformable sampling -> g_mid (split bf16)
    {
        int groups = BSZ * NQ * NH;              // 160000
        sample_kernel<<<groups / 8, 256>>>(refpts);
    }
    // 5) out = mid @ W_out + b_out
    {
        int M = BSZ * NQ, N = EDIM, K = EDIM;
        dim3 grid(N / 128, (M + 127) / 128);
        gemm_bf16x3_kernel<float><<<grid, 512, GEMM_SMEM>>>(
            midh, midl, wh + WOFF_OUT, wl + WOFF_OUT, b_out, out, M, N, K);
    }
}

// round 6
// speedup vs baseline: 1.9382x; 1.4277x over previous
#include <cuda_runtime.h>
#include <cuda_fp16.h>
#include <cstdint>

#define BSZ 2
#define NQ 10000
#define EDIM 256
#define NH 8
#define NL 4
#define NP 8
#define DH 32
#define LEN_VAL 13294
#define NOA 768            // fused off(512) + attn(256) output width

// ---------------- scratch (device globals: allocation-free) ----------------
__device__ __half g_v16[(size_t)BSZ * LEN_VAL * EDIM];   // projected value (fp16)
__device__ __half g_a16[(size_t)BSZ * LEN_VAL * EDIM];   // raw value (fp16)
__device__ __half g_q16[(size_t)BSZ * NQ * EDIM];        // q = query + pos (fp16)
__device__ float  g_offattn[(size_t)BSZ * NQ * NOA];     // [off 512 | attn 256]
__device__ __half g_mid16[(size_t)BSZ * NQ * EDIM];      // sampling result (fp16)
__device__ float  g_bias_oa[NOA];

// fp16 weights [K][N], concatenated: [W_val 256x256][W_oa 256x768][W_out 256x256]
#define WOFF_VAL  0
#define WOFF_OA   65536
#define WOFF_OUT  262144
#define WTOTAL    327680
__device__ __half g_W16[WTOTAL];

__constant__ int c_Hs[NL]    = {100, 50, 25, 13};
__constant__ int c_Ws[NL]    = {100, 50, 25, 13};
__constant__ int c_start[NL] = {0, 10000, 12500, 13125};

// ---------------- helpers ----------------
__device__ __forceinline__ void ldm_x4(uint32_t& r0, uint32_t& r1, uint32_t& r2, uint32_t& r3,
                                       uint32_t addr) {
    asm volatile("ldmatrix.sync.aligned.m8n8.x4.shared.b16 {%0,%1,%2,%3}, [%4];"
                 : "=r"(r0), "=r"(r1), "=r"(r2), "=r"(r3) : "r"(addr));
}

__device__ __forceinline__ void ldm_x4_trans(uint32_t& r0, uint32_t& r1, uint32_t& r2, uint32_t& r3,
                                             uint32_t addr) {
    asm volatile("ldmatrix.sync.aligned.m8n8.x4.trans.shared.b16 {%0,%1,%2,%3}, [%4];"
                 : "=r"(r0), "=r"(r1), "=r"(r2), "=r"(r3) : "r"(addr));
}

__device__ __forceinline__ void mma_f16(float* d, const uint32_t* a, const uint32_t* b) {
    asm volatile("mma.sync.aligned.m16n8k16.row.col.f32.f16.f16.f32 "
                 "{%0,%1,%2,%3},{%4,%5,%6,%7},{%8,%9},{%0,%1,%2,%3};"
                 : "+f"(d[0]), "+f"(d[1]), "+f"(d[2]), "+f"(d[3])
                 : "r"(a[0]), "r"(a[1]), "r"(a[2]), "r"(a[3]), "r"(b[0]), "r"(b[1]));
}

__device__ __forceinline__ void cp_async16(uint32_t dst, const void* src, bool pred) {
    int sz = pred ? 16 : 0;
    asm volatile("cp.async.cg.shared.global [%0], [%1], 16, %2;\n"
                 :: "r"(dst), "l"(src), "r"(sz));
}
#define CP_COMMIT() asm volatile("cp.async.commit_group;\n" ::)
#define CP_WAIT(N)  asm volatile("cp.async.wait_group %0;\n" :: "n"(N))

__device__ __forceinline__ void store2(float* p, float a, float b) {
    *(float2*)p = make_float2(a, b);
}
__device__ __forceinline__ void store2(__half* p, float a, float b) {
    *(__half2*)p = __floats2half2_rn(a, b);
}

// ---------------- prep kernels ----------------
__global__ void convert_weights_kernel(const float* __restrict__ W_val,
                                       const float* __restrict__ W_off,
                                       const float* __restrict__ W_attn,
                                       const float* __restrict__ W_out,
                                       const float* __restrict__ b_off,
                                       const float* __restrict__ b_attn) {
    int i = blockIdx.x * blockDim.x + threadIdx.x;
    if (i >= WTOTAL) return;
    float x;
    if (i < WOFF_OA) {
        x = W_val[i];
    } else if (i < WOFF_OUT) {
        int j = i - WOFF_OA;
        int r = j / NOA, c = j - r * NOA;
        x = (c < 512) ? W_off[r * 512 + c] : W_attn[r * 256 + (c - 512)];
    } else {
        x = W_out[i - WOFF_OUT];
    }
    g_W16[i] = __float2half(x);
    if (i < NOA) g_bias_oa[i] = (i < 512) ? b_off[i] : b_attn[i - 512];
}

__global__ void add_pos_h_kernel(const float* __restrict__ a,
                                 const float* __restrict__ b, int n) {
    int i = blockIdx.x * blockDim.x + threadIdx.x;
    if (i < n) g_q16[i] = __float2half(a[i] + b[i]);
}

__global__ void convert_value_kernel(const float* __restrict__ v, int n) {
    int i = blockIdx.x * blockDim.x + threadIdx.x;
    if (i < n) g_a16[i] = __float2half(v[i]);
}

// ---------------- fp16 tensor-core GEMM, cp.async 4-stage ----------------
// C[M,N] = A[M,256] @ B[256,N] + bias.  BM=128, BN=128, BK=32, 512 threads.
#define SA_STRIDE 40
#define SB_STRIDE 136
#define SA_BYTES  (128 * SA_STRIDE * 2)   // 10240
#define SB_BYTES  (32 * SB_STRIDE * 2)    // 8704
#define NSTAGE 4
#define OFF_A 0
#define OFF_B (NSTAGE * SA_BYTES)
#define GEMM_SMEM (NSTAGE * (SA_BYTES + SB_BYTES))   // 75776

template <typename TOut>
__global__ void __launch_bounds__(512, 1)
gemm_f16_kernel(const __half* __restrict__ A,
                const __half* __restrict__ B,
                const float* __restrict__ bias,
                TOut* __restrict__ C,
                int M, int N) {
    extern __shared__ char smem_raw[];
    const uint32_t sbase = (uint32_t)__cvta_generic_to_shared(smem_raw);

    const int tid  = threadIdx.x;
    const int lane = tid & 31;
    const int wid  = tid >> 5;
    const int warp_m = wid & 3;
    const int warp_n = wid >> 2;

    const int row0 = blockIdx.y * 128;
    const int col0 = blockIdx.x * 128;

    const int a_row = tid >> 2;           // 0..127
    const int a_c8  = (tid & 3) * 8;
    const int b_kr  = tid >> 4;           // 0..31
    const int b_c8  = (tid & 15) * 8;

    const bool a_pred = (row0 + a_row) < M;
    const __half* srcA = A + (size_t)(row0 + a_row) * 256 + a_c8;
    const __half* srcB = B + (size_t)b_kr * N + col0 + b_c8;

    const uint32_t dA = sbase + OFF_A + a_row * (SA_STRIDE * 2) + a_c8 * 2;
    const uint32_t dB = sbase + OFF_B + b_kr * (SB_STRIDE * 2) + b_c8 * 2;

#define ISSUE(J)                                                             \
    {                                                                        \
        int s = (J) & (NSTAGE - 1);                                          \
        int k0 = (J) * 32;                                                   \
        cp_async16(dA + s * SA_BYTES, srcA + k0, a_pred);                    \
        cp_async16(dB + s * SB_BYTES, srcB + (size_t)k0 * N, true);          \
    }

    ISSUE(0); CP_COMMIT();
    ISSUE(1); CP_COMMIT();
    ISSUE(2); CP_COMMIT();

    float acc[2][4][4];
#pragma unroll
    for (int mt = 0; mt < 2; mt++)
#pragma unroll
        for (int nb = 0; nb < 4; nb++)
#pragma unroll
            for (int j = 0; j < 4; j++) acc[mt][nb][j] = 0.f;

    const int NK = 8;
    for (int it = 0; it < NK; ++it) {
        CP_WAIT(2);
        __syncthreads();
        if (it + 3 < NK) ISSUE(it + 3);
        CP_COMMIT();

        const int s = it & (NSTAGE - 1);
        const uint32_t aB = sbase + OFF_A + s * SA_BYTES;
        const uint32_t bB = sbase + OFF_B + s * SB_BYTES;

#pragma unroll
        for (int ks = 0; ks < 2; ks++) {
            uint32_t af[2][4], bf[4][2];
#pragma unroll
            for (int mt = 0; mt < 2; mt++) {
                int row = warp_m * 32 + mt * 16 + (lane & 15);
                int col = ks * 16 + ((lane >> 4) << 3);
                ldm_x4(af[mt][0], af[mt][1], af[mt][2], af[mt][3],
                       aB + row * (SA_STRIDE * 2) + col * 2);
            }
#pragma unroll
            for (int g = 0; g < 2; g++) {
                int kk = ks * 16 + ((lane >> 3) & 1) * 8 + (lane & 7);
                int nn = warp_n * 32 + g * 16 + ((lane >> 4) & 1) * 8;
                uint32_t r0, r1, r2, r3;
                ldm_x4_trans(r0, r1, r2, r3, bB + kk * (SB_STRIDE * 2) + nn * 2);
                bf[2 * g][0] = r0;     bf[2 * g][1] = r1;
                bf[2 * g + 1][0] = r2; bf[2 * g + 1][1] = r3;
            }
#pragma unroll
            for (int mt = 0; mt < 2; mt++)
#pragma unroll
                for (int nb = 0; nb < 4; nb++)
                    mma_f16(acc[mt][nb], af[mt], bf[nb]);
        }
        __syncthreads();
    }
#undef ISSUE

#pragma unroll
    for (int mt = 0; mt < 2; mt++) {
#pragma unroll
        for (int nb = 0; nb < 4; nb++) {
            int gn = col0 + warp_n * 32 + nb * 8 + (lane & 3) * 2;
            float b0 = bias[gn], b1 = bias[gn + 1];
            int gm0 = row0 + warp_m * 32 + mt * 16 + (lane >> 2);
            if (gm0 < M) store2(C + (size_t)gm0 * N + gn, acc[mt][nb][0] + b0, acc[mt][nb][1] + b1);
            int gm1 = gm0 + 8;
            if (gm1 < M) store2(C + (size_t)gm1 * N + gn, acc[mt][nb][2] + b0, acc[mt][nb][3] + b1);
        }
    }
}

// ---------------- deformable sampling v3 (LDG.128 gather) ----------------
// Block = 256 threads = 8 warps, one warp per (b,n,h) group.
// Phase 1: lane i -> sample i metadata (corner half-indices + folded weights) -> smem.
// Phase 2: 4 lanes per sample (8 samples in flight); each lane owns 8 channels,
//          loads 16B per corner; butterfly-reduce across the 8 sample slots.
__global__ void __launch_bounds__(256)
sample_kernel(const float* __restrict__ ref) {
    __shared__ int4   s_ad[8][32];
    __shared__ float4 s_w[8][32];

    const int wlocal = threadIdx.x >> 5;
    const int lane   = threadIdx.x & 31;
    const int gw = blockIdx.x * 8 + wlocal;

    const int h = gw & (NH - 1);
    const int n = (gw >> 3) % NQ;
    const int b = gw / (NQ * NH);
    const long qrow = (long)b * NQ + n;
    const float* oa = g_offattn + qrow * NOA;

    // ---- phase 1 ----
    {
        int l = lane >> 3;
        int Hs = c_Hs[l], Ws = c_Ws[l];
        int ocol = ((h * NL + l) * NP + (lane & 7)) * 2;
        float ox = oa[ocol];
        float oy = oa[ocol + 1];
        float rx = ref[(qrow * NL + l) * 2 + 0];
        float ry = ref[(qrow * NL + l) * 2 + 1];

        float x = rx * (float)Ws + ox - 0.5f;
        float y = ry * (float)Hs + oy - 0.5f;

        float fx0 = floorf(x), fy0 = floorf(y);
        int x0 = (int)fx0, y0 = (int)fy0;
        float wx1 = x - fx0, wy1 = y - fy0;
        float wx0 = 1.f - wx1, wy0 = 1.f - wy1;

        float logit = oa[512 + h * DH + lane];
        float m = logit;
#pragma unroll
        for (int o = 16; o; o >>= 1) m = fmaxf(m, __shfl_xor_sync(0xFFFFFFFFu, m, o));
        float ex = __expf(logit - m);
        float s = ex;
#pragma unroll
        for (int o = 16; o; o >>= 1) s += __shfl_xor_sync(0xFFFFFFFFu, s, o);
        float aw = ex / s;

        int x1 = x0 + 1, y1 = y0 + 1;
        bool vx0 = (x0 >= 0) && (x0 < Ws);
        bool vx1 = (x1 >= 0) && (x1 < Ws);
        bool vy0 = (y0 >= 0) && (y0 < Hs);
        bool vy1 = (y1 >= 0) && (y1 < Hs);

        int base = (b * LEN_VAL + c_start[l]) * EDIM + h * DH;

        int p00 = (vy0 && vx0) ? (y0 * Ws + x0) : 0;
        int p01 = (vy0 && vx1) ? (y0 * Ws + x1) : 0;
        int p10 = (vy1 && vx0) ? (y1 * Ws + x0) : 0;
        int p11 = (vy1 && vx1) ? (y1 * Ws + x1) : 0;

        float w00 = (vy0 && vx0) ? aw * wx0 * wy0 : 0.f;
        float w01 = (vy0 && vx1) ? aw * wx1 * wy0 : 0.f;
        float w10 = (vy1 && vx0) ? aw * wx0 * wy1 : 0.f;
        float w11 = (vy1 && vx1) ? aw * wx1 * wy1 : 0.f;

        s_ad[wlocal][lane] = make_int4(base + p00 * EDIM, base + p01 * EDIM,
                                       base + p10 * EDIM, base + p11 * EDIM);
        s_w[wlocal][lane]  = make_float4(w00, w01, w10, w11);
    }
    __syncwarp();

    // ---- phase 2 ----
    const int slot = lane >> 2;    // 0..7 (sample slot)
    const int q4   = lane & 3;     // channel quad: halfs [8*q4, 8*q4+8)
    const __half* vb = g_v16;

    float2 acc[4];
#pragma unroll
    for (int j = 0; j < 4; j++) acc[j] = make_float2(0.f, 0.f);

#pragma unroll
    for (int it = 0; it < 4; it++) {
        int sIdx = it * 8 + slot;
        int4   ad = s_ad[wlocal][sIdx];
        float4 ww = s_w[wlocal][sIdx];
#pragma unroll
        for (int cn = 0; cn < 4; cn++) {
            int a = (cn == 0) ? ad.x : (cn == 1) ? ad.y : (cn == 2) ? ad.z : ad.w;
            float w = (cn == 0) ? ww.x : (cn == 1) ? ww.y : (cn == 2) ? ww.z : ww.w;
            uint4 u = *(const uint4*)(vb + a + q4 * 8);
            __half2 h0 = *(__half2*)&u.x;
            __half2 h1 = *(__half2*)&u.y;
            __half2 h2 = *(__half2*)&u.z;
            __half2 h3 = *(__half2*)&u.w;
            float2 f;
            f = __half22float2(h0); acc[0].x = fmaf(w, f.x, acc[0].x); acc[0].y = fmaf(w, f.y, acc[0].y);
            f = __half22float2(h1); acc[1].x = fmaf(w, f.x, acc[1].x); acc[1].y = fmaf(w, f.y, acc[1].y);
            f = __half22float2(h2); acc[2].x = fmaf(w, f.x, acc[2].x); acc[2].y = fmaf(w, f.y, acc[2].y);
            f = __half22float2(h3); acc[3].x = fmaf(w, f.x, acc[3].x); acc[3].y = fmaf(w, f.y, acc[3].y);
        }
    }

    // butterfly-reduce across the 8 slots (lane bits 2..4)
#pragma unroll
    for (int o = 4; o <= 16; o <<= 1) {
#pragma unroll
        for (int j = 0; j < 4; j++) {
            acc[j].x += __shfl_xor_sync(0xFFFFFFFFu, acc[j].x, o);
            acc[j].y += __shfl_xor_sync(0xFFFFFFFFu, acc[j].y, o);
        }
    }

    if (lane < 4) {
        __align__(16) __half2 outv[4];
#pragma unroll
        for (int j = 0; j < 4; j++) outv[j] = __floats2half2_rn(acc[j].x, acc[j].y);
        size_t midx = qrow * EDIM + h * DH + q4 * 8;
        *(uint4*)(g_mid16 + midx) = *(uint4*)outv;
    }
}

// ---------------- launch ----------------
extern "C" void kernel_launch(void* const* d_in, const int* in_sizes, int n_in,
                              void* d_out, int out_size) {
    const float* query   = (const float*)d_in[0];
    const float* value   = (const float*)d_in[1];
    const float* qpos    = (const float*)d_in[2];
    const float* refpts  = (const float*)d_in[3];
    const float* W_off   = (const float*)d_in[5];
    const float* b_off   = (const float*)d_in[6];
    const float* W_attn  = (const float*)d_in[7];
    const float* b_attn  = (const float*)d_in[8];
    const float* W_val   = (const float*)d_in[9];
    const float* b_val   = (const float*)d_in[10];
    const float* W_out   = (const float*)d_in[11];
    const float* b_out   = (const float*)d_in[12];
    float* out = (float*)d_out;

    __half *w16, *q16, *a16, *v16, *mid16;
    float *voa, *boa;
    cudaGetSymbolAddress((void**)&w16, g_W16);
    cudaGetSymbolAddress((void**)&q16, g_q16);
    cudaGetSymbolAddress((void**)&a16, g_a16);
    cudaGetSymbolAddress((void**)&v16, g_v16);
    cudaGetSymbolAddress((void**)&mid16, g_mid16);
    cudaGetSymbolAddress((void**)&voa, g_offattn);
    cudaGetSymbolAddress((void**)&boa, g_bias_oa);

    cudaFuncSetAttribute(gemm_f16_kernel<float>,
                         cudaFuncAttributeMaxDynamicSharedMemorySize, GEMM_SMEM);
    cudaFuncSetAttribute(gemm_f16_kernel<__half>,
                         cudaFuncAttributeMaxDynamicSharedMemorySize, GEMM_SMEM);

    // 0) weights -> fp16 (+fused oa bias)
    convert_weights_kernel<<<(WTOTAL + 255) / 256, 256>>>(W_val, W_off, W_attn, W_out,
                                                          b_off, b_attn);
    // 1) q = query + query_pos -> fp16
    {
        int n = BSZ * NQ * EDIM;
        add_pos_h_kernel<<<(n + 255) / 256, 256>>>(query, qpos, n);
    }
    // 1b) raw value -> fp16
    {
        int n = BSZ * LEN_VAL * EDIM;
        convert_value_kernel<<<(n + 255) / 256, 256>>>(value, n);
    }
    // 2) v = value @ W_val + b_val -> fp16
    {
        int M = BSZ * LEN_VAL, N = EDIM;
        dim3 grid(N / 128, (M + 127) / 128);
        gemm_f16_kernel<__half><<<grid, 512, GEMM_SMEM>>>(
            a16, w16 + WOFF_VAL, b_val, v16, M, N);
    }
    // 3) [off|attn] = q @ W_oa + b_oa (N = 768)
    {
        int M = BSZ * NQ, N = NOA;
        dim3 grid(N / 128, (M + 127) / 128);
        gemm_f16_kernel<float><<<grid, 512, GEMM_SMEM>>>(
            q16, w16 + WOFF_OA, boa, voa, M, N);
    }
    // 4) deformable sampling -> g_mid16
    {
        int groups = BSZ * NQ * NH;              // 160000
        sample_kernel<<<groups / 8, 256>>>(refpts);
    }
    // 5) out = mid @ W_out + b_out
    {
        int M = BSZ * NQ, N = EDIM;
        dim3 grid(N / 128, (M + 127) / 128);
        gemm_f16_kernel<float><<<grid, 512, GEMM_SMEM>>>(
            mid16, w16 + WOFF_OUT, b_out, out, M, N);
    }
}